// round 4
// baseline (speedup 1.0000x reference)
#include <cuda_runtime.h>
#include <cuda_bf16.h>

#define NN 50000
#define NE 800000

// Scratch: __device__ globals (no allocation allowed).
// g_y[n*32+u]    = {ys[u], yv[u][0], yv[u][1], yv[u][2]}   (post-lin1, scaled)
// g_midA[n*32+u] = segment-sum of {o_s_a[u], o_v_a[u][0..2]}
// g_midB[n*32+u] = segment-sum of {o_s_b[u], o_v_b[u][0..2]}
__device__ float4 g_y[NN * 32];
__device__ float4 g_midA[NN * 32];
__device__ float4 g_midB[NN * 32];

__device__ __forceinline__ void red_add_f4(float4* p, float4 v) {
    asm volatile("red.global.add.v4.f32 [%0], {%1, %2, %3, %4};"
                 :: "l"(p), "f"(v.x), "f"(v.y), "f"(v.z), "f"(v.w)
                 : "memory");
}

// ---------------------------------------------------------------------------
// Kernel 0: zero the mid accumulators (graph replays re-use them).
// ---------------------------------------------------------------------------
__global__ void zero_mid_kernel() {
    const int total = NN * 32;
    float4 z = make_float4(0.f, 0.f, 0.f, 0.f);
    for (int i = blockIdx.x * blockDim.x + threadIdx.x; i < total;
         i += gridDim.x * blockDim.x) {
        g_midA[i] = z;
        g_midB[i] = z;
    }
}

// ---------------------------------------------------------------------------
// Kernel 1: per-node prep.
//   ys = xs @ W_lin1_s * l1n ; yv = einsum('nui,uw->nwi', xv, W_lin1_v) * l1n
//   sc_s/sc_v (self-connection, one-hot species) written directly into out.
// Warp per node, lane = output channel w.
// ---------------------------------------------------------------------------
__global__ void node_prep_kernel(const float* __restrict__ nf,
                                 const float* __restrict__ nattr,
                                 const float* __restrict__ W1s,
                                 const float* __restrict__ W1v,
                                 const float* __restrict__ Wscs,
                                 const float* __restrict__ Wscv,
                                 float* __restrict__ out) {
    __shared__ float sW1s[1024];   // [u][w]
    __shared__ float sW1v[1024];
    __shared__ float sWs[4096];    // [u][sp][w]
    __shared__ float sWv[4096];
    __shared__ float sRow[8][128];

    const int tid = threadIdx.x;
    for (int i = tid; i < 1024; i += 256) { sW1s[i] = W1s[i]; sW1v[i] = W1v[i]; }
    for (int i = tid; i < 4096; i += 256) { sWs[i]  = Wscs[i]; sWv[i] = Wscv[i]; }
    __syncthreads();

    const int warp = tid >> 5, lane = tid & 31;
    const int nwarps = gridDim.x * 8;
    const float l1n = 0.17677669529663687f;  // 1/sqrt(32)
    const float scn = 0.08838834764831843f;  // 1/sqrt(32*4)

    for (int n = blockIdx.x * 8 + warp; n < NN; n += nwarps) {
        const float* row = nf + (size_t)n * 128;
        for (int i = lane; i < 128; i += 32) sRow[warp][i] = row[i];
        __syncwarp();

        int sp = 0;
#pragma unroll
        for (int v = 0; v < 4; v++)
            if (nattr[n * 4 + v] > 0.5f) sp = v;

        const int w = lane;
        float ys = 0.f, yv0 = 0.f, yv1 = 0.f, yv2 = 0.f;
        float ss = 0.f, sv0 = 0.f, sv1 = 0.f, sv2 = 0.f;
        const float* ws = sWs + sp * 32 + w;
        const float* wv = sWv + sp * 32 + w;
#pragma unroll 8
        for (int u = 0; u < 32; u++) {
            float xs = sRow[warp][u];
            float x0 = sRow[warp][32 + u * 3 + 0];
            float x1 = sRow[warp][32 + u * 3 + 1];
            float x2 = sRow[warp][32 + u * 3 + 2];
            float a = sW1s[u * 32 + w];
            float b = sW1v[u * 32 + w];
            ys += xs * a; yv0 += x0 * b; yv1 += x1 * b; yv2 += x2 * b;
            float c = ws[u * 128];
            float d = wv[u * 128];
            ss += xs * c; sv0 += x0 * d; sv1 += x1 * d; sv2 += x2 * d;
        }

        g_y[n * 32 + w] = make_float4(ys * l1n, yv0 * l1n, yv1 * l1n, yv2 * l1n);

        float* orow = out + (size_t)n * 128;
        orow[w] = ss * scn;
        orow[32 + w * 3 + 0] = sv0 * scn;
        orow[32 + w * 3 + 1] = sv1 * scn;
        orow[32 + w * 3 + 2] = sv2 * scn;
        __syncwarp();
    }
}

// ---------------------------------------------------------------------------
// Kernel 2: edge kernel. Warp per edge, lane = channel u.
//   h = silu(eb @ fc_w1 / sqrt(8)); w = h @ fc_w2 / sqrt(8) -> w00..w11
//   gather y[src], compute edge outputs, vector-RED into mid[dst].
// ---------------------------------------------------------------------------
__global__ void edge_kernel(const float* __restrict__ eb,
                            const float* __restrict__ ea,
                            const int* __restrict__ ei,
                            const float* __restrict__ fw1,
                            const float* __restrict__ fw2) {
    __shared__ float sfw1[64];     // [k][j]
    __shared__ float sfw2[1024];   // [j][c*32+u]
    const int tid = threadIdx.x;
    if (tid < 64) sfw1[tid] = fw1[tid];
    for (int i = tid; i < 1024; i += 256) sfw2[i] = fw2[i];
    __syncthreads();

    const int warp = tid >> 5, lane = tid & 31;
    const int nwarps = gridDim.x * 8;
    const float is8 = 0.3535533905932738f;  // 1/sqrt(8)
    const float IS3 = 0.5773502691896258f;  // 1/sqrt(3)
    const int u = lane;

    for (int e = blockIdx.x * 8 + warp; e < NE; e += nwarps) {
        const int src = ei[e];
        const int dst = ei[NE + e];

        float ebv[8];
#pragma unroll
        for (int k = 0; k < 8; k++) ebv[k] = eb[e * 8 + k];

        float h[8];
#pragma unroll
        for (int j = 0; j < 8; j++) {
            float acc = 0.f;
#pragma unroll
            for (int k = 0; k < 8; k++) acc += ebv[k] * sfw1[k * 8 + j];
            acc *= is8;
            h[j] = acc / (1.f + __expf(-acc));   // silu
        }

        float w00 = 0.f, w01 = 0.f, w10 = 0.f, w11 = 0.f;
#pragma unroll
        for (int j = 0; j < 8; j++) {
            const float hv = h[j];
            const float* p = sfw2 + j * 128 + u;
            w00 += hv * p[0];
            w01 += hv * p[32];
            w10 += hv * p[64];
            w11 += hv * p[96];
        }
        w00 *= is8; w01 *= is8; w10 *= is8; w11 *= is8;

        const float4 y = g_y[src * 32 + u];
        const float a0  = ea[e * 4 + 0];
        const float a10 = ea[e * 4 + 1];
        const float a11 = ea[e * 4 + 2];
        const float a12 = ea[e * 4 + 3];

        const float es = y.x;
        const float osa = w00 * es * a0;
        const float dotv = y.y * a10 + y.z * a11 + y.w * a12;
        const float osb = w11 * dotv * IS3;
        const float wes = w01 * es;
        const float w10a0 = w10 * a0;

        float4 A = make_float4(osa, wes * a10, wes * a11, wes * a12);
        float4 B = make_float4(osb, w10a0 * y.y, w10a0 * y.z, w10a0 * y.w);

        red_add_f4(&g_midA[dst * 32 + u], A);
        red_add_f4(&g_midB[dst * 32 + u], B);
    }
}

// ---------------------------------------------------------------------------
// Kernel 3: per-node output.
//   out_s += (mid_s @ W_lin2_s) * inv * l2n ; out_v likewise (sc already in out)
// Warp per node, lane = output channel w. mid staged in shared.
// ---------------------------------------------------------------------------
__global__ void node_out_kernel(const float* __restrict__ W2s,
                                const float* __restrict__ W2v,
                                float* __restrict__ out) {
    __shared__ float sW2s[2048];   // [u][w], u in [0,64)
    __shared__ float sW2v[2048];
    __shared__ float4 sMid[8][64];

    const int tid = threadIdx.x;
    for (int i = tid; i < 2048; i += 256) { sW2s[i] = W2s[i]; sW2v[i] = W2v[i]; }
    __syncthreads();

    const int warp = tid >> 5, lane = tid & 31;
    const int nwarps = gridDim.x * 8;
    const float c = 0.25f * 0.125f;  // inv=1/sqrt(16) * l2n=1/sqrt(64)

    for (int n = blockIdx.x * 8 + warp; n < NN; n += nwarps) {
        sMid[warp][lane]      = g_midA[n * 32 + lane];
        sMid[warp][32 + lane] = g_midB[n * 32 + lane];
        __syncwarp();

        const int w = lane;
        float os = 0.f, ov0 = 0.f, ov1 = 0.f, ov2 = 0.f;
#pragma unroll 8
        for (int uu = 0; uu < 64; uu++) {
            float4 m = sMid[warp][uu];
            float a = sW2s[uu * 32 + w];
            float b = sW2v[uu * 32 + w];
            os  += m.x * a;
            ov0 += m.y * b;
            ov1 += m.z * b;
            ov2 += m.w * b;
        }

        float* orow = out + (size_t)n * 128;
        orow[w]                += os  * c;
        orow[32 + w * 3 + 0]   += ov0 * c;
        orow[32 + w * 3 + 1]   += ov1 * c;
        orow[32 + w * 3 + 2]   += ov2 * c;
        __syncwarp();
    }
}

// ---------------------------------------------------------------------------
extern "C" void kernel_launch(void* const* d_in, const int* in_sizes, int n_in,
                              void* d_out, int out_size) {
    const float* nf    = (const float*)d_in[0];   // node_features (N, 128)
    const float* nattr = (const float*)d_in[1];   // node_attr (N, 4)
    const float* eb    = (const float*)d_in[2];   // edge_embedding (E, 8)
    const float* ea    = (const float*)d_in[3];   // edge_attr (E, 4)
    const int*   ei    = (const int*)d_in[4];     // edge_index (2, E)
    const float* W1s   = (const float*)d_in[5];
    const float* W1v   = (const float*)d_in[6];
    const float* fw1   = (const float*)d_in[7];
    const float* fw2   = (const float*)d_in[8];
    const float* W2s   = (const float*)d_in[9];
    const float* W2v   = (const float*)d_in[10];
    const float* Wscs  = (const float*)d_in[11];
    const float* Wscv  = (const float*)d_in[12];
    float* out = (float*)d_out;

    zero_mid_kernel<<<1184, 256>>>();
    node_prep_kernel<<<1184, 256>>>(nf, nattr, W1s, W1v, Wscs, Wscv, out);
    edge_kernel<<<2048, 256>>>(eb, ea, ei, fw1, fw2);
    node_out_kernel<<<1184, 256>>>(W2s, W2v, out);
}

// round 5
// speedup vs baseline: 1.4504x; 1.4504x over previous
#include <cuda_runtime.h>
#include <cuda_bf16.h>

#define NN 50000
#define NE 800000

// Scratch: __device__ globals (no allocation allowed).
// g_y[n*32+u]    = {ys[u], yv[u][0..2]}   (post-lin1, scaled)
// g_midA/B[n*32+u] = segment sums of edge outputs (A: o_s_a/o_v_a, B: o_s_b/o_v_b)
__device__ float4 g_y[NN * 32];
__device__ float4 g_midA[NN * 32];
__device__ float4 g_midB[NN * 32];

__device__ __forceinline__ void red_add_f4(float4* p, float4 v) {
    asm volatile("red.global.add.v4.f32 [%0], {%1, %2, %3, %4};"
                 :: "l"(p), "f"(v.x), "f"(v.y), "f"(v.z), "f"(v.w)
                 : "memory");
}

// ---------------------------------------------------------------------------
// Kernel 1: per-node prep + zero mid accumulators.
//   ys/yv = lin1(x) ; sc_s/sc_v (self-connection) written directly into out.
// Warp per node, lane = output channel w. Paired weights packed as float2.
// ---------------------------------------------------------------------------
__global__ void node_prep_kernel(const float* __restrict__ nf,
                                 const float* __restrict__ nattr,
                                 const float* __restrict__ W1s,
                                 const float* __restrict__ W1v,
                                 const float* __restrict__ Wscs,
                                 const float* __restrict__ Wscv,
                                 float* __restrict__ out) {
    __shared__ float2 sW1[1024];   // [u][w] -> {W1s, W1v}
    __shared__ float2 sWsc[4096];  // [u][sp][w] -> {Wscs, Wscv}
    __shared__ float sRow[8][128];

    const int tid = threadIdx.x;
    for (int i = tid; i < 1024; i += 256) sW1[i] = make_float2(W1s[i], W1v[i]);
    for (int i = tid; i < 4096; i += 256) sWsc[i] = make_float2(Wscs[i], Wscv[i]);
    __syncthreads();

    const int warp = tid >> 5, lane = tid & 31;
    const int nwarps = gridDim.x * 8;
    const float l1n = 0.17677669529663687f;  // 1/sqrt(32)
    const float scn = 0.08838834764831843f;  // 1/sqrt(32*4)
    const float4 z4 = make_float4(0.f, 0.f, 0.f, 0.f);

    for (int n = blockIdx.x * 8 + warp; n < NN; n += nwarps) {
        const float* row = nf + (size_t)n * 128;
        for (int i = lane; i < 128; i += 32) sRow[warp][i] = row[i];

        // zero the mid accumulators for this node (replaces zero_mid kernel)
        g_midA[n * 32 + lane] = z4;
        g_midB[n * 32 + lane] = z4;
        __syncwarp();

        int sp = 0;
#pragma unroll
        for (int v = 0; v < 4; v++)
            if (nattr[n * 4 + v] > 0.5f) sp = v;

        const int w = lane;
        float ys = 0.f, yv0 = 0.f, yv1 = 0.f, yv2 = 0.f;
        float ss = 0.f, sv0 = 0.f, sv1 = 0.f, sv2 = 0.f;
        const float2* wsc = sWsc + sp * 32 + w;
#pragma unroll 8
        for (int u = 0; u < 32; u++) {
            float xs = sRow[warp][u];
            float x0 = sRow[warp][32 + u * 3 + 0];
            float x1 = sRow[warp][32 + u * 3 + 1];
            float x2 = sRow[warp][32 + u * 3 + 2];
            float2 ab = sW1[u * 32 + w];
            ys  = fmaf(xs, ab.x, ys);
            yv0 = fmaf(x0, ab.y, yv0);
            yv1 = fmaf(x1, ab.y, yv1);
            yv2 = fmaf(x2, ab.y, yv2);
            float2 cd = wsc[u * 128];
            ss  = fmaf(xs, cd.x, ss);
            sv0 = fmaf(x0, cd.y, sv0);
            sv1 = fmaf(x1, cd.y, sv1);
            sv2 = fmaf(x2, cd.y, sv2);
        }

        g_y[n * 32 + w] = make_float4(ys * l1n, yv0 * l1n, yv1 * l1n, yv2 * l1n);

        float* orow = out + (size_t)n * 128;
        orow[w] = ss * scn;
        orow[32 + w * 3 + 0] = sv0 * scn;
        orow[32 + w * 3 + 1] = sv1 * scn;
        orow[32 + w * 3 + 2] = sv2 * scn;
        __syncwarp();
    }
}

// ---------------------------------------------------------------------------
// Kernel 2: edge kernel. Warp per edge, lane = channel u.
// h (8 values, identical across lanes) is computed ONCE per warp:
// lanes 0-7 each compute one h[j] (2 MUFU warp-ops total instead of 16),
// then shuffled to everyone. w-projection stays lane-parallel over u.
// ---------------------------------------------------------------------------
__global__ void edge_kernel(const float* __restrict__ eb,
                            const float* __restrict__ ea,
                            const int* __restrict__ ei,
                            const float* __restrict__ fw1,
                            const float* __restrict__ fw2) {
    __shared__ float sfw1[64];     // [k][j]
    __shared__ float sfw2[1024];   // [j][c*32+u]
    const int tid = threadIdx.x;
    if (tid < 64) sfw1[tid] = fw1[tid];
    for (int i = tid; i < 1024; i += 256) sfw2[i] = fw2[i];
    __syncthreads();

    const int warp = tid >> 5, lane = tid & 31;
    const int nwarps = gridDim.x * 8;
    const float is8 = 0.3535533905932738f;  // 1/sqrt(8)
    const float IS3 = 0.5773502691896258f;  // 1/sqrt(3)
    const int u = lane;
    const float* w1col = sfw1 + (lane & 7);

    for (int e = blockIdx.x * 8 + warp; e < NE; e += nwarps) {
        const int src = __ldg(ei + e);
        const int dst = __ldg(ei + NE + e);

        // issue long-latency loads early
        const float4 y  = __ldg(&g_y[src * 32 + u]);                   // gather (L2-resident)
        const float4 av = __ldg((const float4*)(ea + (size_t)e * 4));  // 1 broadcast LDG.128
        float ebv = (lane < 8) ? __ldg(eb + (size_t)e * 8 + lane) : 0.f;

        // cooperative MLP: lane j (mod 8) computes h[j]
        float acc = 0.f;
#pragma unroll
        for (int k = 0; k < 8; k++)
            acc = fmaf(__shfl_sync(0xffffffffu, ebv, k), w1col[k * 8], acc);
        acc *= is8;
        float hv = __fdividef(acc, 1.f + __expf(-acc));   // silu, 2 MUFU/warp

        float w00 = 0.f, w01 = 0.f, w10 = 0.f, w11 = 0.f;
#pragma unroll
        for (int j = 0; j < 8; j++) {
            const float hj = __shfl_sync(0xffffffffu, hv, j);
            const float* p = sfw2 + j * 128 + u;
            w00 = fmaf(hj, p[0],  w00);
            w01 = fmaf(hj, p[32], w01);
            w10 = fmaf(hj, p[64], w10);
            w11 = fmaf(hj, p[96], w11);
        }
        w00 *= is8; w01 *= is8; w10 *= is8; w11 *= is8;

        const float es    = y.x;
        const float osa   = w00 * es * av.x;
        const float dotv  = fmaf(y.y, av.y, fmaf(y.z, av.z, y.w * av.w));
        const float osb   = w11 * dotv * IS3;
        const float wes   = w01 * es;
        const float w10a0 = w10 * av.x;

        float4 A = make_float4(osa, wes * av.y, wes * av.z, wes * av.w);
        float4 B = make_float4(osb, w10a0 * y.y, w10a0 * y.z, w10a0 * y.w);

        red_add_f4(&g_midA[dst * 32 + u], A);
        red_add_f4(&g_midB[dst * 32 + u], B);
    }
}

// ---------------------------------------------------------------------------
// Kernel 3: per-node output.
//   out_s += (mid_s @ W_lin2_s) * inv * l2n ; out_v likewise (sc already in out)
// Warp per node, lane = output channel w. Paired weights packed as float2.
// ---------------------------------------------------------------------------
__global__ void node_out_kernel(const float* __restrict__ W2s,
                                const float* __restrict__ W2v,
                                float* __restrict__ out) {
    __shared__ float2 sW2[2048];   // [u][w] -> {W2s, W2v}, u in [0,64)
    __shared__ float4 sMid[8][64];

    const int tid = threadIdx.x;
    for (int i = tid; i < 2048; i += 256) sW2[i] = make_float2(W2s[i], W2v[i]);
    __syncthreads();

    const int warp = tid >> 5, lane = tid & 31;
    const int nwarps = gridDim.x * 8;
    const float c = 0.25f * 0.125f;  // 1/sqrt(16) * 1/sqrt(64)

    for (int n = blockIdx.x * 8 + warp; n < NN; n += nwarps) {
        sMid[warp][lane]      = g_midA[n * 32 + lane];
        sMid[warp][32 + lane] = g_midB[n * 32 + lane];
        __syncwarp();

        const int w = lane;
        float os = 0.f, ov0 = 0.f, ov1 = 0.f, ov2 = 0.f;
#pragma unroll 16
        for (int uu = 0; uu < 64; uu++) {
            float4 m  = sMid[warp][uu];
            float2 ab = sW2[uu * 32 + w];
            os  = fmaf(m.x, ab.x, os);
            ov0 = fmaf(m.y, ab.y, ov0);
            ov1 = fmaf(m.z, ab.y, ov1);
            ov2 = fmaf(m.w, ab.y, ov2);
        }

        float* orow = out + (size_t)n * 128;
        orow[w]              += os  * c;
        orow[32 + w * 3 + 0] += ov0 * c;
        orow[32 + w * 3 + 1] += ov1 * c;
        orow[32 + w * 3 + 2] += ov2 * c;
        __syncwarp();
    }
}

// ---------------------------------------------------------------------------
extern "C" void kernel_launch(void* const* d_in, const int* in_sizes, int n_in,
                              void* d_out, int out_size) {
    const float* nf    = (const float*)d_in[0];   // node_features (N, 128)
    const float* nattr = (const float*)d_in[1];   // node_attr (N, 4)
    const float* eb    = (const float*)d_in[2];   // edge_embedding (E, 8)
    const float* ea    = (const float*)d_in[3];   // edge_attr (E, 4)
    const int*   ei    = (const int*)d_in[4];     // edge_index (2, E)
    const float* W1s   = (const float*)d_in[5];
    const float* W1v   = (const float*)d_in[6];
    const float* fw1   = (const float*)d_in[7];
    const float* fw2   = (const float*)d_in[8];
    const float* W2s   = (const float*)d_in[9];
    const float* W2v   = (const float*)d_in[10];
    const float* Wscs  = (const float*)d_in[11];
    const float* Wscv  = (const float*)d_in[12];
    float* out = (float*)d_out;

    node_prep_kernel<<<1184, 256>>>(nf, nattr, W1s, W1v, Wscs, Wscv, out);
    edge_kernel<<<1184, 256>>>(eb, ea, ei, fw1, fw2);
    node_out_kernel<<<1184, 256>>>(W2s, W2v, out);
}

// round 8
// speedup vs baseline: 1.6095x; 1.1097x over previous
#include <cuda_runtime.h>
#include <cuda_bf16.h>

#define NN 50000
#define NE 800000

// Scratch: __device__ globals (no allocation allowed).
// g_y[n*32+u]    = {ys[u], yv[u][0..2]}   (post-lin1, scaled)
// g_midA/B[n*32+u] = segment sums of edge outputs (A: o_s_a/o_v_a, B: o_s_b/o_v_b)
__device__ float4 g_y[NN * 32];
__device__ float4 g_midA[NN * 32];
__device__ float4 g_midB[NN * 32];

__device__ __forceinline__ void red_add_f4(float4* p, float4 v) {
    asm volatile("red.global.add.v4.f32 [%0], {%1, %2, %3, %4};"
                 :: "l"(p), "f"(v.x), "f"(v.y), "f"(v.z), "f"(v.w)
                 : "memory");
}

// ---------------------------------------------------------------------------
// Kernel 1: per-node prep + zero mid accumulators.
//   ys/yv = lin1(x) ; sc_s/sc_v (self-connection) written directly into out.
// Warp per node, lane = output channel w.
// Node row staged as PACKED float4 {xs[u], xv[u][0..2]} so the inner loop
// does 1 LDS.128 broadcast per u instead of 4 scalar broadcasts.
// ---------------------------------------------------------------------------
__global__ void node_prep_kernel(const float* __restrict__ nf,
                                 const float* __restrict__ nattr,
                                 const float* __restrict__ W1s,
                                 const float* __restrict__ W1v,
                                 const float* __restrict__ Wscs,
                                 const float* __restrict__ Wscv,
                                 float* __restrict__ out) {
    __shared__ float2 sW1[1024];   // [u][w] -> {W1s, W1v}
    __shared__ float2 sWsc[4096];  // [u][sp][w] -> {Wscs, Wscv}
    __shared__ float4 sRow[8][32]; // packed {xs, xv0, xv1, xv2} per u

    const int tid = threadIdx.x;
    for (int i = tid; i < 1024; i += 256) sW1[i] = make_float2(W1s[i], W1v[i]);
    for (int i = tid; i < 4096; i += 256) sWsc[i] = make_float2(Wscs[i], Wscv[i]);
    __syncthreads();

    const int warp = tid >> 5, lane = tid & 31;
    const int nwarps = gridDim.x * 8;
    const float l1n = 0.17677669529663687f;  // 1/sqrt(32)
    const float scn = 0.08838834764831843f;  // 1/sqrt(32*4)
    const float4 z4 = make_float4(0.f, 0.f, 0.f, 0.f);

    for (int n = blockIdx.x * 8 + warp; n < NN; n += nwarps) {
        const float* row = nf + (size_t)n * 128;
        // lane u packs {row[u], row[32+3u+0..2]}
        {
            float xs = __ldg(row + lane);
            float x0 = __ldg(row + 32 + lane * 3 + 0);
            float x1 = __ldg(row + 32 + lane * 3 + 1);
            float x2 = __ldg(row + 32 + lane * 3 + 2);
            sRow[warp][lane] = make_float4(xs, x0, x1, x2);
        }

        // zero the mid accumulators for this node (replaces zero_mid kernel)
        g_midA[n * 32 + lane] = z4;
        g_midB[n * 32 + lane] = z4;
        __syncwarp();

        int sp = 0;
#pragma unroll
        for (int v = 0; v < 4; v++)
            if (nattr[n * 4 + v] > 0.5f) sp = v;

        const int w = lane;
        float ys = 0.f, yv0 = 0.f, yv1 = 0.f, yv2 = 0.f;
        float ss = 0.f, sv0 = 0.f, sv1 = 0.f, sv2 = 0.f;
        const float2* wsc = sWsc + sp * 32 + w;
#pragma unroll 8
        for (int u = 0; u < 32; u++) {
            float4 x = sRow[warp][u];            // 1 LDS.128 broadcast
            float2 ab = sW1[u * 32 + w];
            ys  = fmaf(x.x, ab.x, ys);
            yv0 = fmaf(x.y, ab.y, yv0);
            yv1 = fmaf(x.z, ab.y, yv1);
            yv2 = fmaf(x.w, ab.y, yv2);
            float2 cd = wsc[u * 128];
            ss  = fmaf(x.x, cd.x, ss);
            sv0 = fmaf(x.y, cd.y, sv0);
            sv1 = fmaf(x.z, cd.y, sv1);
            sv2 = fmaf(x.w, cd.y, sv2);
        }

        g_y[n * 32 + w] = make_float4(ys * l1n, yv0 * l1n, yv1 * l1n, yv2 * l1n);

        float* orow = out + (size_t)n * 128;
        orow[w] = ss * scn;
        orow[32 + w * 3 + 0] = sv0 * scn;
        orow[32 + w * 3 + 1] = sv1 * scn;
        orow[32 + w * 3 + 2] = sv2 * scn;
        __syncwarp();
    }
}

// ---------------------------------------------------------------------------
// Kernel 2: edge kernel. Warp per edge, lane = channel u.
// ALL weights live in registers:
//   w1r[k]    = fc_w1[k][lane&7]          (8 regs, first MLP layer)
//   w2r[j][c] = fc_w2[j][c*32 + lane]     (32 regs, second MLP layer)
// No shared memory, no per-edge LDS. h computed cooperatively (lanes 0-7
// via shfl), 2 MUFU warp-ops per edge for silu.
// ---------------------------------------------------------------------------
__global__ void __launch_bounds__(256) edge_kernel(
                            const float* __restrict__ eb,
                            const float* __restrict__ ea,
                            const int* __restrict__ ei,
                            const float* __restrict__ fw1,
                            const float* __restrict__ fw2) {
    const int tid = threadIdx.x;
    const int warp = tid >> 5, lane = tid & 31;
    const int nwarps = gridDim.x * 8;
    const float is8 = 0.3535533905932738f;  // 1/sqrt(8)
    const float IS3 = 0.5773502691896258f;  // 1/sqrt(3)
    const int u = lane;

    // loop-invariant weight preload into registers
    float w1r[8];
#pragma unroll
    for (int k = 0; k < 8; k++) w1r[k] = __ldg(fw1 + k * 8 + (lane & 7));
    float w2r[32];
#pragma unroll
    for (int j = 0; j < 8; j++)
#pragma unroll
        for (int c = 0; c < 4; c++)
            w2r[j * 4 + c] = __ldg(fw2 + j * 128 + c * 32 + u);

    for (int e = blockIdx.x * 8 + warp; e < NE; e += nwarps) {
        const int src = __ldg(ei + e);
        const int dst = __ldg(ei + NE + e);

        // issue long-latency loads early
        const float4 y  = __ldg(&g_y[src * 32 + u]);                   // gather (L2-resident)
        const float4 av = __ldg((const float4*)(ea + (size_t)e * 4));  // 1 broadcast LDG.128
        float ebv = (lane < 8) ? __ldg(eb + (size_t)e * 8 + lane) : 0.f;

        // cooperative MLP layer 1: lane j (mod 8) computes h[j]
        float acc = 0.f;
#pragma unroll
        for (int k = 0; k < 8; k++)
            acc = fmaf(__shfl_sync(0xffffffffu, ebv, k), w1r[k], acc);
        acc *= is8;
        float hv = __fdividef(acc, 1.f + __expf(-acc));   // silu, 2 MUFU/warp

        // layer 2: pure register FFMA
        float w00 = 0.f, w01 = 0.f, w10 = 0.f, w11 = 0.f;
#pragma unroll
        for (int j = 0; j < 8; j++) {
            const float hj = __shfl_sync(0xffffffffu, hv, j);
            w00 = fmaf(hj, w2r[j * 4 + 0], w00);
            w01 = fmaf(hj, w2r[j * 4 + 1], w01);
            w10 = fmaf(hj, w2r[j * 4 + 2], w10);
            w11 = fmaf(hj, w2r[j * 4 + 3], w11);
        }
        w00 *= is8; w01 *= is8; w10 *= is8; w11 *= is8;

        const float es    = y.x;
        const float osa   = w00 * es * av.x;
        const float dotv  = fmaf(y.y, av.y, fmaf(y.z, av.z, y.w * av.w));
        const float osb   = w11 * dotv * IS3;
        const float wes   = w01 * es;
        const float w10a0 = w10 * av.x;

        float4 A = make_float4(osa, wes * av.y, wes * av.z, wes * av.w);
        float4 B = make_float4(osb, w10a0 * y.y, w10a0 * y.z, w10a0 * y.w);

        red_add_f4(&g_midA[dst * 32 + u], A);
        red_add_f4(&g_midB[dst * 32 + u], B);
    }
}

// ---------------------------------------------------------------------------
// Kernel 3: per-node output.
//   out_s += (mid_s @ W_lin2_s) * inv * l2n ; out_v likewise (sc already in out)
// Warp per node, lane = output channel w.
// ---------------------------------------------------------------------------
__global__ void node_out_kernel(const float* __restrict__ W2s,
                                const float* __restrict__ W2v,
                                float* __restrict__ out) {
    __shared__ float2 sW2[2048];   // [u][w] -> {W2s, W2v}, u in [0,64)
    __shared__ float4 sMid[8][64];

    const int tid = threadIdx.x;
    for (int i = tid; i < 2048; i += 256) sW2[i] = make_float2(W2s[i], W2v[i]);
    __syncthreads();

    const int warp = tid >> 5, lane = tid & 31;
    const int nwarps = gridDim.x * 8;
    const float c = 0.25f * 0.125f;  // 1/sqrt(16) * 1/sqrt(64)

    for (int n = blockIdx.x * 8 + warp; n < NN; n += nwarps) {
        sMid[warp][lane]      = g_midA[n * 32 + lane];
        sMid[warp][32 + lane] = g_midB[n * 32 + lane];
        __syncwarp();

        const int w = lane;
        float os = 0.f, ov0 = 0.f, ov1 = 0.f, ov2 = 0.f;
#pragma unroll 16
        for (int uu = 0; uu < 64; uu++) {
            float4 m  = sMid[warp][uu];
            float2 ab = sW2[uu * 32 + w];
            os  = fmaf(m.x, ab.x, os);
            ov0 = fmaf(m.y, ab.y, ov0);
            ov1 = fmaf(m.z, ab.y, ov1);
            ov2 = fmaf(m.w, ab.y, ov2);
        }

        float* orow = out + (size_t)n * 128;
        orow[w]              += os  * c;
        orow[32 + w * 3 + 0] += ov0 * c;
        orow[32 + w * 3 + 1] += ov1 * c;
        orow[32 + w * 3 + 2] += ov2 * c;
        __syncwarp();
    }
}

// ---------------------------------------------------------------------------
extern "C" void kernel_launch(void* const* d_in, const int* in_sizes, int n_in,
                              void* d_out, int out_size) {
    const float* nf    = (const float*)d_in[0];   // node_features (N, 128)
    const float* nattr = (const float*)d_in[1];   // node_attr (N, 4)
    const float* eb    = (const float*)d_in[2];   // edge_embedding (E, 8)
    const float* ea    = (const float*)d_in[3];   // edge_attr (E, 4)
    const int*   ei    = (const int*)d_in[4];     // edge_index (2, E)
    const float* W1s   = (const float*)d_in[5];
    const float* W1v   = (const float*)d_in[6];
    const float* fw1   = (const float*)d_in[7];
    const float* fw2   = (const float*)d_in[8];
    const float* W2s   = (const float*)d_in[9];
    const float* W2v   = (const float*)d_in[10];
    const float* Wscs  = (const float*)d_in[11];
    const float* Wscv  = (const float*)d_in[12];
    float* out = (float*)d_out;

    node_prep_kernel<<<1184, 256>>>(nf, nattr, W1s, W1v, Wscs, Wscv, out);
    edge_kernel<<<1184, 256>>>(eb, ea, ei, fw1, fw2);
    node_out_kernel<<<1184, 256>>>(W2s, W2v, out);
}